// round 4
// baseline (speedup 1.0000x reference)
#include <cuda_runtime.h>
#include <cuda_bf16.h>
#include <stdint.h>

#define B_DIM 32
#define S_DIM 2048
#define MD 128
#define LB 64
#define NW 2041          // S - RANK + 1
#define WTILE 128
#define NTILES 512       // 32 batches x 16 chunks

#define RAW_ROWS 136     // 135 needed + 1 dummy
#define RAW_F32 (RAW_ROWS * MD)              // 17408 floats
#define AT_U32  (MD * 68)                    // 8704 u32
#define SMEM_BYTES (RAW_F32 * 4 + AT_U32 * 4 + 256 * 4 + 16)

// Scratch (device globals: no allocations allowed)
__device__ float g_C64[LB * MD];   // C[w%64][m] = sum_n M[n][m]*Nk[l][n]
__device__ float g_G[MD * MD];     // G[m][m'] = sum_n M[n][m]*M[n][m']
__device__ float g_nksq[LB];
__device__ float g_part[NTILES];
__device__ unsigned int g_count;   // zero-init; reset by last block each call

// ---------------- K1: setup (prep + gram merged) -------------------
__global__ void k_setup(const float* __restrict__ M,
                        const float* __restrict__ A,
                        const float* __restrict__ Bb) {
    int t = threadIdx.x;   // 0..127
    if (blockIdx.x < LB) {
        int l = blockIdx.x;                 // 0..63
        __shared__ float nk[MD];
        __shared__ float red[MD];
        float v = A[t * LB + l] * Bb[l * MD + t];   // Nk[l][n=t]
        nk[t] = v;
        red[t] = v * v;
        __syncthreads();
        float c = 0.f;
#pragma unroll 8
        for (int n = 0; n < MD; n++) c += M[n * MD + t] * nk[n];
        g_C64[l * MD + t] = c;
        for (int s = 64; s > 0; s >>= 1) {
            if (t < s) red[t] += red[t + s];
            __syncthreads();
        }
        if (t == 0) g_nksq[l] = red[0];
    } else {
        int m = blockIdx.x - LB;            // 0..127
        float s = 0.f;
#pragma unroll 8
        for (int n = 0; n < MD; n++) s += M[n * MD + m] * M[n * MD + t];
        g_G[m * MD + t] = s;
    }
}

// ---------------- K2: main fused kernel --------------------
__global__ void __launch_bounds__(256, 2) k_main(const float* __restrict__ seq,
                                                 float* __restrict__ out) {
    extern __shared__ char smem[];
    float*    raw  = reinterpret_cast<float*>(smem);                 // [136][128]
    uint32_t* At   = reinterpret_cast<uint32_t*>(smem + RAW_F32 * 4); // [128][68]
    float*    sred = reinterpret_cast<float*>(smem + RAW_F32 * 4 + AT_U32 * 4);
    unsigned int* s_ticket =
        reinterpret_cast<unsigned int*>(smem + RAW_F32 * 4 + AT_U32 * 4 + 256 * 4);

    int tid  = threadIdx.x;
    int lane = tid & 31;
    int wid  = tid >> 5;

    int tile  = blockIdx.x;
    int b     = tile >> 4;
    int chunk = tile & 15;
    int w0    = chunk * WTILE;
    int wt    = min(WTILE, NW - w0);

    // ---- phase 0: bulk load raw tile (136 rows x 128 f32) into SMEM ----
    {
        const float4* gsrc = reinterpret_cast<const float4*>(
            seq + ((size_t)b * S_DIM + w0) * MD);
#pragma unroll
        for (int i = 0; i < 17; i++) {
            int idx  = tid + i * 256;     // float4 index within tile
            int row  = idx >> 5;          // 0..135
            float4 v = make_float4(0.f, 0.f, 0.f, 0.f);
            if (w0 + row < S_DIM) v = __ldg(&gsrc[idx]);
            reinterpret_cast<float4*>(raw)[idx] = v;
        }
    }
    __syncthreads();

    float cross = 0.f;

    // ---- phase 1: prefix-sum sliding window + bf16 transpose store ----
    {
        int m  = tid & 127;
        int wb = (tid >> 7) * 64;        // 0 or 64
        const float* rs = raw + wb * MD + m;

        float ring[8];
        float P = 0.f;
#pragma unroll
        for (int j = 0; j < 8; j++) { ring[j] = P; P += rs[j * MD]; }
        // now ring[j] = P_j (j=0..7), P = P_8

#pragma unroll
        for (int w = 0; w < 64; w += 2) {
            float a0 = (wb + w < wt) ? (P - ring[w & 7]) * 0.125f : 0.f;
            cross += a0 * __ldg(&g_C64[w * MD + m]);   // (w0+wb+w)%64 == w
            ring[w & 7] = P;
            P += rs[(w + 8) * MD];

            float a1 = (wb + w + 1 < wt) ? (P - ring[(w + 1) & 7]) * 0.125f : 0.f;
            cross += a1 * __ldg(&g_C64[(w + 1) * MD + m]);
            if (w + 1 < 63) {
                ring[(w + 1) & 7] = P;
                P += rs[(w + 9) * MD];
            }

            __nv_bfloat162 pk = __floats2bfloat162_rn(a0, a1); // low = even k
            At[m * 68 + ((wb + w) >> 1)] = *reinterpret_cast<uint32_t*>(&pk);
        }
    }
    __syncthreads();

    // ---- phase 2: Gram += At * At^T  (mma.sync m16n8k16 bf16) ----
    float acc[2][8][4];
#pragma unroll
    for (int a = 0; a < 2; a++)
#pragma unroll
        for (int bb = 0; bb < 8; bb++)
#pragma unroll
            for (int c = 0; c < 4; c++) acc[a][bb][c] = 0.f;

    int wm = (wid & 3) << 5;   // m offset (4 warps along M)
    int wn = (wid >> 2) << 6;  // n offset (2 warps along N)
    int g  = lane >> 2;
    int tc = lane & 3;
#pragma unroll
    for (int ks = 0; ks < 8; ks++) {
        int kc = ks * 8 + tc;  // u32 column index (k/2)
        uint32_t af[2][4], bf[8][2];
#pragma unroll
        for (int mt = 0; mt < 2; mt++) {
            int r = wm + mt * 16 + g;
            af[mt][0] = At[r * 68 + kc];
            af[mt][1] = At[(r + 8) * 68 + kc];
            af[mt][2] = At[r * 68 + kc + 4];
            af[mt][3] = At[(r + 8) * 68 + kc + 4];
        }
#pragma unroll
        for (int nt = 0; nt < 8; nt++) {
            int r = wn + nt * 8 + g;
            bf[nt][0] = At[r * 68 + kc];
            bf[nt][1] = At[r * 68 + kc + 4];
        }
#pragma unroll
        for (int nt = 0; nt < 8; nt++)
#pragma unroll
            for (int mt = 0; mt < 2; mt++)
                asm volatile(
                    "mma.sync.aligned.m16n8k16.row.col.f32.bf16.bf16.f32 "
                    "{%0,%1,%2,%3}, {%4,%5,%6,%7}, {%8,%9}, {%0,%1,%2,%3};"
                    : "+f"(acc[mt][nt][0]), "+f"(acc[mt][nt][1]),
                      "+f"(acc[mt][nt][2]), "+f"(acc[mt][nt][3])
                    : "r"(af[mt][0]), "r"(af[mt][1]),
                      "r"(af[mt][2]), "r"(af[mt][3]),
                      "r"(bf[nt][0]), "r"(bf[nt][1]));
    }

    // ---- epilogue: dot partial Gram (registers) with G ----
    float dot = 0.f;
#pragma unroll
    for (int mt = 0; mt < 2; mt++)
#pragma unroll
        for (int nt = 0; nt < 8; nt++) {
            int r = wm + mt * 16 + g;
            int c = wn + nt * 8 + 2 * tc;
            dot += acc[mt][nt][0] * __ldg(&g_G[r * MD + c]);
            dot += acc[mt][nt][1] * __ldg(&g_G[r * MD + c + 1]);
            dot += acc[mt][nt][2] * __ldg(&g_G[(r + 8) * MD + c]);
            dot += acc[mt][nt][3] * __ldg(&g_G[(r + 8) * MD + c + 1]);
        }

    // ---- block reduce (dot - 2*cross) ----
    sred[tid] = dot - 2.f * cross;
    __syncthreads();
    for (int s = 128; s > 0; s >>= 1) {
        if (tid < s) sred[tid] += sred[tid + s];
        __syncthreads();
    }

    // ---- last-block final reduction (replay-safe ticket) ----
    if (tid == 0) {
        g_part[blockIdx.x] = sred[0];
        __threadfence();
        *s_ticket = atomicAdd(&g_count, 1u);
    }
    __syncthreads();
    if (*s_ticket == NTILES - 1) {
        float v = g_part[tid] + g_part[tid + 256];
        if (tid < LB) {
            int cnt = (NW - 1 - tid) / 64 + 1;   // #windows with w%64 == tid
            v += (float)B_DIM * (float)cnt * g_nksq[tid];
        }
        sred[tid] = v;
        __syncthreads();
        for (int s = 128; s > 0; s >>= 1) {
            if (tid < s) sred[tid] += sred[tid + s];
            __syncthreads();
        }
        if (tid == 0) {
            out[0] = sred[0] * (float)(1.0 / (32.0 * 2041.0 * 128.0));
            g_count = 0u;   // reset for next graph replay
        }
    }
}

extern "C" void kernel_launch(void* const* d_in, const int* in_sizes, int n_in,
                              void* d_out, int out_size) {
    (void)in_sizes; (void)n_in; (void)out_size;
    const float* seq = (const float*)d_in[0];
    const float* M   = (const float*)d_in[1];
    const float* A   = (const float*)d_in[2];
    const float* Bb  = (const float*)d_in[3];
    float* out = (float*)d_out;

    static bool attr_done = false;
    if (!attr_done) {
        cudaFuncSetAttribute(k_main, cudaFuncAttributeMaxDynamicSharedMemorySize,
                             SMEM_BYTES);
        attr_done = true;
    }

    k_setup<<<LB + MD, MD>>>(M, A, Bb);
    k_main<<<NTILES, 256, SMEM_BYTES>>>(seq, out);
}